// round 9
// baseline (speedup 1.0000x reference)
#include <cuda_runtime.h>
#include <cuda_fp16.h>
#include <cstdint>

#define DIMX 4096
#define QH   32
#define KVH  8
#define HD   128
#define SEQ  2048
#define BSZ  2
#define MTOK (BSZ*SEQ)      // 4096 tokens
#define KVD  (KVH*HD)       // 1024

// ---------------- fp16 scratch (static; no allocation) ----------------
__device__ __half g_xh [(size_t)MTOK * DIMX];
__device__ __half g_wqh[(size_t)DIMX * DIMX];
__device__ __half g_wkh[(size_t)DIMX * KVD];
__device__ __half g_wvh[(size_t)DIMX * KVD];
__device__ __half g_woh[(size_t)DIMX * DIMX];
__device__ __half g_Qh [(size_t)MTOK * DIMX];
__device__ __half g_Kh [(size_t)MTOK * KVD];
__device__ __half g_Vh [(size_t)MTOK * KVD];
__device__ __half g_Ah [(size_t)MTOK * DIMX];

// ---------------- helpers ----------------
__device__ __forceinline__ void ldsm4(unsigned* r, uint32_t a) {
    asm volatile("ldmatrix.sync.aligned.m8n8.x4.shared.b16 {%0,%1,%2,%3}, [%4];\n"
                 : "=r"(r[0]), "=r"(r[1]), "=r"(r[2]), "=r"(r[3]) : "r"(a));
}
__device__ __forceinline__ void ldsm4t(unsigned* r, uint32_t a) {
    asm volatile("ldmatrix.sync.aligned.m8n8.x4.trans.shared.b16 {%0,%1,%2,%3}, [%4];\n"
                 : "=r"(r[0]), "=r"(r[1]), "=r"(r[2]), "=r"(r[3]) : "r"(a));
}
__device__ __forceinline__ void hmma(float* c, const unsigned* a, const unsigned* b) {
    asm volatile("mma.sync.aligned.m16n8k16.row.col.f32.f16.f16.f32 "
                 "{%0,%1,%2,%3}, {%4,%5,%6,%7}, {%8,%9}, {%0,%1,%2,%3};\n"
                 : "+f"(c[0]), "+f"(c[1]), "+f"(c[2]), "+f"(c[3])
                 : "r"(a[0]), "r"(a[1]), "r"(a[2]), "r"(a[3]), "r"(b[0]), "r"(b[1]));
}
__device__ __forceinline__ void cpa16(uint32_t dst, const void* src) {
    asm volatile("cp.async.cg.shared.global [%0], [%1], 16;\n" :: "r"(dst), "l"(src));
}
#define CP_COMMIT() asm volatile("cp.async.commit_group;\n")
#define CP_WAIT1()  asm volatile("cp.async.wait_group 1;\n")
#define CP_WAIT0()  asm volatile("cp.async.wait_group 0;\n")

__device__ __forceinline__ void st2(float* p, float x, float y)  { *(float2*)p = make_float2(x, y); }
__device__ __forceinline__ void st2(__half* p, float x, float y) { *(__half2*)p = __floats2half2_rn(x, y); }
__device__ __forceinline__ unsigned packh(float lo, float hi) {
    __half2 h = __floats2half2_rn(lo, hi);
    return *(unsigned*)&h;
}

// ---------------- f32 -> f16 convert ----------------
__global__ __launch_bounds__(256) void f2h(const float4* __restrict__ in,
                                           __half2* __restrict__ out, int n4) {
    int i = blockIdx.x * blockDim.x + threadIdx.x;
    if (i < n4) {
        float4 v = in[i];
        out[2 * i]     = __floats2half2_rn(v.x, v.y);
        out[2 * i + 1] = __floats2half2_rn(v.z, v.w);
    }
}

// ================= GEMM fp16: C[M,N] = A[M,K] @ W[K,N] + bias =================
// BM=128 BN=128 BK=32, 256 threads (8 warps, 4x2), warp tile 32x64.
// 3-stage cp.async ring, ONE __syncthreads per k-tile, prefetch distance 2.
#define APITCH 40     // 32 + 8 halves pad
#define BPITCH 136    // 128 + 8 halves pad
#define ASTG   (128 * APITCH)            // 5120 halves
#define BSTG   (32 * BPITCH)             // 4352 halves
#define GSTGH  (ASTG + BSTG)             // 9472 halves per stage
#define GSMEM_BYTES (3 * GSTGH * 2)      // 56832 B

template<typename OutT>
__global__ __launch_bounds__(256, 2) void gemm16(
    const __half* __restrict__ A, const __half* __restrict__ W,
    const float* __restrict__ bias, OutT* __restrict__ C,
    int M, int N, int K)
{
    extern __shared__ __half smem[];
    const uint32_t sb = (uint32_t)__cvta_generic_to_shared(smem);

    const int tid = threadIdx.x, lane = tid & 31, warp = tid >> 5;
    const int wm = (warp >> 1) * 32, wn = (warp & 1) * 64;
    const int bm = blockIdx.y * 128, bn = blockIdx.x * 128;
    const int g = lane >> 2, q = lane & 3;
    const int t15 = lane & 15, hi8 = (lane >> 4) * 8;

    float acc[2][8][4];
    #pragma unroll
    for (int mt = 0; mt < 2; mt++)
        #pragma unroll
        for (int nt = 0; nt < 8; nt++)
            #pragma unroll
            for (int i = 0; i < 4; i++) acc[mt][nt][i] = 0.f;

    auto As = [&](int s, int r, int c) { return sb + (uint32_t)(s * GSTGH + r * APITCH + c) * 2u; };
    auto Bs = [&](int s, int r, int c) { return sb + (uint32_t)(s * GSTGH + ASTG + r * BPITCH + c) * 2u; };

    auto load_stage = [&](int s, int k0) {
        #pragma unroll
        for (int i = 0; i < 2; i++) {
            int id = tid + i * 256;
            int r = id >> 2, c = (id & 3) * 8;
            cpa16(As(s, r, c), A + (size_t)(bm + r) * K + k0 + c);
        }
        #pragma unroll
        for (int i = 0; i < 2; i++) {
            int id = tid + i * 256;
            int r = id >> 4, c = (id & 15) * 8;
            cpa16(Bs(s, r, c), W + (size_t)(k0 + r) * N + bn + c);
        }
        CP_COMMIT();
    };

    // prologue: tiles 0 and 1 in flight
    load_stage(0, 0);
    load_stage(1, 32);

    const int T = K >> 5;
    for (int t = 0; t < T; t++) {
        if (t + 1 < T) CP_WAIT1();      // tile t's group retired (t+1 may be in flight)
        else           CP_WAIT0();
        __syncthreads();                // all warps done with tile t-1 -> slot (t+2)%3 free
        const int pf = t + 2;
        if (pf < T) load_stage(pf % 3, pf * 32);

        const int s = t % 3;
        #pragma unroll
        for (int kk = 0; kk < 32; kk += 16) {
            unsigned a[2][4], bf[4][4];
            #pragma unroll
            for (int mt = 0; mt < 2; mt++)
                ldsm4(a[mt], As(s, wm + mt * 16 + t15, kk + hi8));
            #pragma unroll
            for (int nn = 0; nn < 4; nn++)
                ldsm4t(bf[nn], Bs(s, kk + t15, wn + nn * 16 + hi8));
            #pragma unroll
            for (int mt = 0; mt < 2; mt++)
                #pragma unroll
                for (int nn = 0; nn < 4; nn++) {
                    hmma(acc[mt][2 * nn],     a[mt], &bf[nn][0]);
                    hmma(acc[mt][2 * nn + 1], a[mt], &bf[nn][2]);
                }
        }
    }

    #pragma unroll
    for (int mt = 0; mt < 2; mt++) {
        int r0 = bm + wm + mt * 16 + g;
        #pragma unroll
        for (int nt = 0; nt < 8; nt++) {
            int c0 = bn + wn + nt * 8 + q * 2;
            float b0 = bias[c0], b1 = bias[c0 + 1];
            st2(C + (size_t)r0 * N + c0,       acc[mt][nt][0] + b0, acc[mt][nt][1] + b1);
            st2(C + (size_t)(r0 + 8) * N + c0, acc[mt][nt][2] + b0, acc[mt][nt][3] + b1);
        }
    }
}

// ================= Flash attention fp16 (Br=128, Bc=64, d=128) =================
// UNCHANGED from R7 (1530us run): P in registers, occ 1, no reg cap.
#define FDP 136
#define QS0 0
#define KS0 17408
#define VS0 34816
#define FLASH_SMEM_BYTES (52224 * 2)   // 104448

__global__ __launch_bounds__(256, 1) void flash16(
    const __half* __restrict__ Q, const __half* __restrict__ Kp,
    const __half* __restrict__ Vp, __half* __restrict__ O)
{
    extern __shared__ __half fsm[];
    const uint32_t sb = (uint32_t)__cvta_generic_to_shared(fsm);

    const int tid = threadIdx.x, lane = tid & 31, warp = tid >> 5;
    const int g = lane >> 2, q4 = lane & 3;
    const int t15 = lane & 15, hi8 = (lane >> 4) * 8;
    const int krow = ((lane >> 4) << 3) | (lane & 7);
    const int kc8 = ((lane >> 3) & 1) * 8;
    const int gh = blockIdx.y;
    const int b = gh >> 5, h = gh & 31, kvh = h >> 2;
    const int q0 = blockIdx.x * 128;
    const int base = warp * 16;
    const int row = base + g;
    const float scale = 0.08838834764831845f;   // 1/sqrt(128)

    auto QS = [&](int r, int c)        { return sb + (uint32_t)(QS0 + r * FDP + c) * 2u; };
    auto KS = [&](int s, int r, int c) { return sb + (uint32_t)(KS0 + s * 8704 + r * FDP + c) * 2u; };
    auto VS = [&](int s, int r, int c) { return sb + (uint32_t)(VS0 + s * 8704 + r * FDP + c) * 2u; };

    auto load_kv = [&](int s, int j) {
        const __half* Kb = Kp + ((size_t)(b * SEQ + j * 64)) * KVD + kvh * HD;
        const __half* Vb = Vp + ((size_t)(b * SEQ + j * 64)) * KVD + kvh * HD;
        #pragma unroll
        for (int i = 0; i < 4; i++) {
            int id = tid + i * 256;
            int r = id >> 4, c = (id & 15) * 8;
            cpa16(KS(s, r, c), Kb + (size_t)r * KVD + c);
            cpa16(VS(s, r, c), Vb + (size_t)r * KVD + c);
        }
        CP_COMMIT();
    };

    load_kv(0, 0);

    // Q tile -> smem (vectorized)
    const __half* Qb = Q + ((size_t)(b * SEQ + q0)) * DIMX + h * HD;
    #pragma unroll
    for (int i = 0; i < 8; i++) {
        int id = tid + i * 256;
        int r = id >> 4, c = (id & 15) * 8;
        *(uint4*)(fsm + QS0 + r * FDP + c) = *(const uint4*)(Qb + (size_t)r * DIMX + c);
    }

    float m0 = -1e30f, m1 = -1e30f, l0 = 0.f, l1 = 0.f;
    float o[16][4];
    #pragma unroll
    for (int nt = 0; nt < 16; nt++)
        #pragma unroll
        for (int i = 0; i < 4; i++) o[nt][i] = 0.f;

    const int TJ = SEQ / 64;
    for (int j = 0; j < TJ; j++) {
        if (j + 1 < TJ) { load_kv((j + 1) & 1, j + 1); CP_WAIT1(); }
        else            { CP_WAIT0(); }
        __syncthreads();
        const int buf = j & 1;

        // ---- S = Q K^T (16x64 per warp) ----
        float s[8][4];
        #pragma unroll
        for (int nt = 0; nt < 8; nt++)
            #pragma unroll
            for (int i = 0; i < 4; i++) s[nt][i] = 0.f;

        #pragma unroll
        for (int kk = 0; kk < HD; kk += 16) {
            unsigned a[4], bk[4][4];
            ldsm4(a, QS(base + t15, kk + hi8));
            #pragma unroll
            for (int nn = 0; nn < 4; nn++)
                ldsm4(bk[nn], KS(buf, nn * 16 + krow, kk + kc8));
            #pragma unroll
            for (int nn = 0; nn < 4; nn++) {
                hmma(s[2 * nn],     a, &bk[nn][0]);
                hmma(s[2 * nn + 1], a, &bk[nn][2]);
            }
        }
        #pragma unroll
        for (int nt = 0; nt < 8; nt++)
            #pragma unroll
            for (int i = 0; i < 4; i++) s[nt][i] *= scale;

        // ---- online softmax (rows `row`, `row+8`) ----
        float rm0 = -1e30f, rm1 = -1e30f;
        #pragma unroll
        for (int nt = 0; nt < 8; nt++) {
            rm0 = fmaxf(rm0, fmaxf(s[nt][0], s[nt][1]));
            rm1 = fmaxf(rm1, fmaxf(s[nt][2], s[nt][3]));
        }
        rm0 = fmaxf(rm0, __shfl_xor_sync(0xffffffffu, rm0, 1));
        rm0 = fmaxf(rm0, __shfl_xor_sync(0xffffffffu, rm0, 2));
        rm1 = fmaxf(rm1, __shfl_xor_sync(0xffffffffu, rm1, 1));
        rm1 = fmaxf(rm1, __shfl_xor_sync(0xffffffffu, rm1, 2));

        float mn0 = fmaxf(m0, rm0), mn1 = fmaxf(m1, rm1);
        float sc0 = __expf(m0 - mn0), sc1 = __expf(m1 - mn1);
        float ls0 = 0.f, ls1 = 0.f;

        // P in registers: C-frag pairs packed directly as m16n8k16 A-frags.
        unsigned pa[4][4];
        #pragma unroll
        for (int nt = 0; nt < 8; nt++) {
            float p0 = __expf(s[nt][0] - mn0), p1 = __expf(s[nt][1] - mn0);
            float p2 = __expf(s[nt][2] - mn1), p3 = __expf(s[nt][3] - mn1);
            ls0 += p0 + p1; ls1 += p2 + p3;
            pa[nt >> 1][(nt & 1) * 2 + 0] = packh(p0, p1);
            pa[nt >> 1][(nt & 1) * 2 + 1] = packh(p2, p3);
        }
        ls0 += __shfl_xor_sync(0xffffffffu, ls0, 1);
        ls0 += __shfl_xor_sync(0xffffffffu, ls0, 2);
        ls1 += __shfl_xor_sync(0xffffffffu, ls1, 1);
        ls1 += __shfl_xor_sync(0xffffffffu, ls1, 2);

        l0 = l0 * sc0 + ls0; l1 = l1 * sc1 + ls1;
        m0 = mn0; m1 = mn1;
        #pragma unroll
        for (int nt = 0; nt < 16; nt++) {
            o[nt][0] *= sc0; o[nt][1] *= sc0;
            o[nt][2] *= sc1; o[nt][3] *= sc1;
        }

        // ---- O += P V (16x128 per warp) ----
        #pragma unroll
        for (int kb = 0; kb < 4; kb++) {
            unsigned bv[8][4];
            #pragma unroll
            for (int nn = 0; nn < 8; nn++)
                ldsm4t(bv[nn], VS(buf, kb * 16 + t15, nn * 16 + hi8));
            #pragma unroll
            for (int nn = 0; nn < 8; nn++) {
                hmma(o[2 * nn],     pa[kb], &bv[nn][0]);
                hmma(o[2 * nn + 1], pa[kb], &bv[nn][2]);
            }
        }
        __syncthreads();
    }

    const float i0 = 1.f / l0, i1 = 1.f / l1;
    __half* Ob = O + ((size_t)(b * SEQ + q0 + row)) * DIMX + h * HD;
    #pragma unroll
    for (int nt = 0; nt < 16; nt++) {
        int c = nt * 8 + 2 * q4;
        *(__half2*)(Ob + c) = __floats2half2_rn(o[nt][0] * i0, o[nt][1] * i0);
        *(__half2*)(Ob + (size_t)8 * DIMX + c) = __floats2half2_rn(o[nt][2] * i1, o[nt][3] * i1);
    }
}

// ================= launch =================
extern "C" void kernel_launch(void* const* d_in, const int* in_sizes, int n_in,
                              void* d_out, int out_size)
{
    const float* x    = (const float*)d_in[0];
    const float* wq_w = (const float*)d_in[1];
    const float* wq_b = (const float*)d_in[2];
    const float* wk_w = (const float*)d_in[3];
    const float* wk_b = (const float*)d_in[4];
    const float* wv_w = (const float*)d_in[5];
    const float* wv_b = (const float*)d_in[6];
    const float* wo_w = (const float*)d_in[7];
    const float* wo_b = (const float*)d_in[8];
    float* out = (float*)d_out;

    __half *xh, *wqh, *wkh, *wvh, *woh, *Qh, *Kh, *Vh, *Ah;
    cudaGetSymbolAddress((void**)&xh,  g_xh);
    cudaGetSymbolAddress((void**)&wqh, g_wqh);
    cudaGetSymbolAddress((void**)&wkh, g_wkh);
    cudaGetSymbolAddress((void**)&wvh, g_wvh);
    cudaGetSymbolAddress((void**)&woh, g_woh);
    cudaGetSymbolAddress((void**)&Qh,  g_Qh);
    cudaGetSymbolAddress((void**)&Kh,  g_Kh);
    cudaGetSymbolAddress((void**)&Vh,  g_Vh);
    cudaGetSymbolAddress((void**)&Ah,  g_Ah);

    cudaFuncSetAttribute(flash16, cudaFuncAttributeMaxDynamicSharedMemorySize, FLASH_SMEM_BYTES);
    cudaFuncSetAttribute(gemm16<__half>, cudaFuncAttributeMaxDynamicSharedMemorySize, GSMEM_BYTES);
    cudaFuncSetAttribute(gemm16<float>,  cudaFuncAttributeMaxDynamicSharedMemorySize, GSMEM_BYTES);

    dim3 blk(256);
    {
        int n4;
        n4 = MTOK * DIMX / 4; f2h<<<n4 / 256, blk>>>((const float4*)x,    (__half2*)xh,  n4);
        n4 = DIMX * DIMX / 4; f2h<<<n4 / 256, blk>>>((const float4*)wq_w, (__half2*)wqh, n4);
        n4 = DIMX * KVD  / 4; f2h<<<n4 / 256, blk>>>((const float4*)wk_w, (__half2*)wkh, n4);
        n4 = DIMX * KVD  / 4; f2h<<<n4 / 256, blk>>>((const float4*)wv_w, (__half2*)wvh, n4);
        n4 = DIMX * DIMX / 4; f2h<<<n4 / 256, blk>>>((const float4*)wo_w, (__half2*)woh, n4);
    }

    gemm16<__half><<<dim3(DIMX / 128, MTOK / 128), blk, GSMEM_BYTES>>>(xh, wqh, wq_b, Qh, MTOK, DIMX, DIMX);
    gemm16<__half><<<dim3(KVD  / 128, MTOK / 128), blk, GSMEM_BYTES>>>(xh, wkh, wk_b, Kh, MTOK, KVD,  DIMX);
    gemm16<__half><<<dim3(KVD  / 128, MTOK / 128), blk, GSMEM_BYTES>>>(xh, wvh, wv_b, Vh, MTOK, KVD,  DIMX);
    flash16<<<dim3(SEQ / 128, BSZ * QH), blk, FLASH_SMEM_BYTES>>>(Qh, Kh, Vh, Ah);
    gemm16<float><<<dim3(DIMX / 128, MTOK / 128), blk, GSMEM_BYTES>>>(Ah, woh, wo_b, out, MTOK, DIMX, DIMX);
}

// round 14
// speedup vs baseline: 1.6239x; 1.6239x over previous
#include <cuda_runtime.h>
#include <cuda_fp16.h>
#include <cstdint>

#define DIMX 4096
#define QH   32
#define KVH  8
#define HD   128
#define SEQ  2048
#define BSZ  2
#define MTOK (BSZ*SEQ)      // 4096 tokens
#define KVD  (KVH*HD)       // 1024

// ---------------- fp16 scratch (static; no allocation) ----------------
__device__ __half g_xh [(size_t)MTOK * DIMX];
__device__ __half g_wqh[(size_t)DIMX * DIMX];
__device__ __half g_wkh[(size_t)DIMX * KVD];
__device__ __half g_wvh[(size_t)DIMX * KVD];
__device__ __half g_woh[(size_t)DIMX * DIMX];
__device__ __half g_Qh [(size_t)MTOK * DIMX];
__device__ __half g_Kh [(size_t)MTOK * KVD];
__device__ __half g_Vh [(size_t)MTOK * KVD];
__device__ __half g_Ah [(size_t)MTOK * DIMX];

// ---------------- helpers ----------------
__device__ __forceinline__ void ldsm4(unsigned* r, uint32_t a) {
    asm volatile("ldmatrix.sync.aligned.m8n8.x4.shared.b16 {%0,%1,%2,%3}, [%4];\n"
                 : "=r"(r[0]), "=r"(r[1]), "=r"(r[2]), "=r"(r[3]) : "r"(a));
}
__device__ __forceinline__ void ldsm4t(unsigned* r, uint32_t a) {
    asm volatile("ldmatrix.sync.aligned.m8n8.x4.trans.shared.b16 {%0,%1,%2,%3}, [%4];\n"
                 : "=r"(r[0]), "=r"(r[1]), "=r"(r[2]), "=r"(r[3]) : "r"(a));
}
__device__ __forceinline__ void hmma(float* c, const unsigned* a, const unsigned* b) {
    asm volatile("mma.sync.aligned.m16n8k16.row.col.f32.f16.f16.f32 "
                 "{%0,%1,%2,%3}, {%4,%5,%6,%7}, {%8,%9}, {%0,%1,%2,%3};\n"
                 : "+f"(c[0]), "+f"(c[1]), "+f"(c[2]), "+f"(c[3])
                 : "r"(a[0]), "r"(a[1]), "r"(a[2]), "r"(a[3]), "r"(b[0]), "r"(b[1]));
}
__device__ __forceinline__ void cpa16(uint32_t dst, const void* src) {
    asm volatile("cp.async.cg.shared.global [%0], [%1], 16;\n" :: "r"(dst), "l"(src));
}
#define CP_COMMIT() asm volatile("cp.async.commit_group;\n")
#define CP_WAIT1()  asm volatile("cp.async.wait_group 1;\n")
#define CP_WAIT0()  asm volatile("cp.async.wait_group 0;\n")

__device__ __forceinline__ void st2(float* p, float x, float y)  { *(float2*)p = make_float2(x, y); }
__device__ __forceinline__ void st2(__half* p, float x, float y) { *(__half2*)p = __floats2half2_rn(x, y); }
__device__ __forceinline__ unsigned packh(float lo, float hi) {
    __half2 h = __floats2half2_rn(lo, hi);
    return *(unsigned*)&h;
}

// ---------------- f32 -> f16 convert ----------------
__global__ __launch_bounds__(256) void f2h(const float4* __restrict__ in,
                                           __half2* __restrict__ out, int n4) {
    int i = blockIdx.x * blockDim.x + threadIdx.x;
    if (i < n4) {
        float4 v = in[i];
        out[2 * i]     = __floats2half2_rn(v.x, v.y);
        out[2 * i + 1] = __floats2half2_rn(v.z, v.w);
    }
}

// ================= GEMM fp16: C[M,N] = A[M,K] @ W[K,N] + bias =================
// BM=128 BN=128 BK=64, 256 threads (8 warps, 4x2), warp tile 32x64.
// 2-stage cp.async double buffer, R7-proven ordering (issue -> wait1 -> sync ->
// compute -> sync). BK=64 halves barrier/wait count per unit MMA work.
#define APITCH 72     // 64 + 8 halves pad (144B stride, ldmatrix conflict-free)
#define BPITCH 136    // 128 + 8 halves pad
#define ASTG   (128 * APITCH)            // 9216 halves
#define BSTG   (64 * BPITCH)             // 8704 halves
#define GSTGH  (ASTG + BSTG)             // 17920 halves per stage
#define GSMEM_BYTES (2 * GSTGH * 2)      // 71680 B

template<typename OutT>
__global__ __launch_bounds__(256, 2) void gemm16(
    const __half* __restrict__ A, const __half* __restrict__ W,
    const float* __restrict__ bias, OutT* __restrict__ C,
    int M, int N, int K)
{
    extern __shared__ __half smem[];
    const uint32_t sb = (uint32_t)__cvta_generic_to_shared(smem);

    const int tid = threadIdx.x, lane = tid & 31, warp = tid >> 5;
    const int wm = (warp >> 1) * 32, wn = (warp & 1) * 64;
    const int bm = blockIdx.y * 128, bn = blockIdx.x * 128;
    const int g = lane >> 2, q = lane & 3;
    const int t15 = lane & 15, hi8 = (lane >> 4) * 8;

    float acc[2][8][4];
    #pragma unroll
    for (int mt = 0; mt < 2; mt++)
        #pragma unroll
        for (int nt = 0; nt < 8; nt++)
            #pragma unroll
            for (int i = 0; i < 4; i++) acc[mt][nt][i] = 0.f;

    auto As = [&](int s, int r, int c) { return sb + (uint32_t)(s * GSTGH + r * APITCH + c) * 2u; };
    auto Bs = [&](int s, int r, int c) { return sb + (uint32_t)(s * GSTGH + ASTG + r * BPITCH + c) * 2u; };

    auto load_stage = [&](int s, int k0) {
        #pragma unroll
        for (int i = 0; i < 4; i++) {          // A tile 128x64 halves
            int id = tid + i * 256;
            int r = id >> 3, c = (id & 7) * 8;
            cpa16(As(s, r, c), A + (size_t)(bm + r) * K + k0 + c);
        }
        #pragma unroll
        for (int i = 0; i < 4; i++) {          // B tile 64x128 halves
            int id = tid + i * 256;
            int r = id >> 4, c = (id & 15) * 8;
            cpa16(Bs(s, r, c), W + (size_t)(k0 + r) * N + bn + c);
        }
        CP_COMMIT();
    };

    load_stage(0, 0);
    const int T = K >> 6;
    for (int t = 0; t < T; t++) {
        if (t + 1 < T) { load_stage((t + 1) & 1, (t + 1) * 64); CP_WAIT1(); }
        else           { CP_WAIT0(); }
        __syncthreads();
        const int s = t & 1;
        #pragma unroll
        for (int kk = 0; kk < 64; kk += 16) {
            unsigned a[2][4], bf[4][4];
            #pragma unroll
            for (int mt = 0; mt < 2; mt++)
                ldsm4(a[mt], As(s, wm + mt * 16 + t15, kk + hi8));
            #pragma unroll
            for (int nn = 0; nn < 4; nn++)
                ldsm4t(bf[nn], Bs(s, kk + t15, wn + nn * 16 + hi8));
            #pragma unroll
            for (int mt = 0; mt < 2; mt++)
                #pragma unroll
                for (int nn = 0; nn < 4; nn++) {
                    hmma(acc[mt][2 * nn],     a[mt], &bf[nn][0]);
                    hmma(acc[mt][2 * nn + 1], a[mt], &bf[nn][2]);
                }
        }
        __syncthreads();
    }

    #pragma unroll
    for (int mt = 0; mt < 2; mt++) {
        int r0 = bm + wm + mt * 16 + g;
        #pragma unroll
        for (int nt = 0; nt < 8; nt++) {
            int c0 = bn + wn + nt * 8 + q * 2;
            float b0 = bias[c0], b1 = bias[c0 + 1];
            st2(C + (size_t)r0 * N + c0,       acc[mt][nt][0] + b0, acc[mt][nt][1] + b1);
            st2(C + (size_t)(r0 + 8) * N + c0, acc[mt][nt][2] + b0, acc[mt][nt][3] + b1);
        }
    }
}

// ================= Flash attention fp16 (Br=128, Bc=64, d=128) =================
// UNCHANGED from R7 (1530us run): P in registers, occ 1, no reg cap.
#define FDP 136
#define QS0 0
#define KS0 17408
#define VS0 34816
#define FLASH_SMEM_BYTES (52224 * 2)   // 104448

__global__ __launch_bounds__(256, 1) void flash16(
    const __half* __restrict__ Q, const __half* __restrict__ Kp,
    const __half* __restrict__ Vp, __half* __restrict__ O)
{
    extern __shared__ __half fsm[];
    const uint32_t sb = (uint32_t)__cvta_generic_to_shared(fsm);

    const int tid = threadIdx.x, lane = tid & 31, warp = tid >> 5;
    const int g = lane >> 2, q4 = lane & 3;
    const int t15 = lane & 15, hi8 = (lane >> 4) * 8;
    const int krow = ((lane >> 4) << 3) | (lane & 7);
    const int kc8 = ((lane >> 3) & 1) * 8;
    const int gh = blockIdx.y;
    const int b = gh >> 5, h = gh & 31, kvh = h >> 2;
    const int q0 = blockIdx.x * 128;
    const int base = warp * 16;
    const int row = base + g;
    const float scale = 0.08838834764831845f;   // 1/sqrt(128)

    auto QS = [&](int r, int c)        { return sb + (uint32_t)(QS0 + r * FDP + c) * 2u; };
    auto KS = [&](int s, int r, int c) { return sb + (uint32_t)(KS0 + s * 8704 + r * FDP + c) * 2u; };
    auto VS = [&](int s, int r, int c) { return sb + (uint32_t)(VS0 + s * 8704 + r * FDP + c) * 2u; };

    auto load_kv = [&](int s, int j) {
        const __half* Kb = Kp + ((size_t)(b * SEQ + j * 64)) * KVD + kvh * HD;
        const __half* Vb = Vp + ((size_t)(b * SEQ + j * 64)) * KVD + kvh * HD;
        #pragma unroll
        for (int i = 0; i < 4; i++) {
            int id = tid + i * 256;
            int r = id >> 4, c = (id & 15) * 8;
            cpa16(KS(s, r, c), Kb + (size_t)r * KVD + c);
            cpa16(VS(s, r, c), Vb + (size_t)r * KVD + c);
        }
        CP_COMMIT();
    };

    load_kv(0, 0);

    // Q tile -> smem (vectorized)
    const __half* Qb = Q + ((size_t)(b * SEQ + q0)) * DIMX + h * HD;
    #pragma unroll
    for (int i = 0; i < 8; i++) {
        int id = tid + i * 256;
        int r = id >> 4, c = (id & 15) * 8;
        *(uint4*)(fsm + QS0 + r * FDP + c) = *(const uint4*)(Qb + (size_t)r * DIMX + c);
    }

    float m0 = -1e30f, m1 = -1e30f, l0 = 0.f, l1 = 0.f;
    float o[16][4];
    #pragma unroll
    for (int nt = 0; nt < 16; nt++)
        #pragma unroll
        for (int i = 0; i < 4; i++) o[nt][i] = 0.f;

    const int TJ = SEQ / 64;
    for (int j = 0; j < TJ; j++) {
        if (j + 1 < TJ) { load_kv((j + 1) & 1, j + 1); CP_WAIT1(); }
        else            { CP_WAIT0(); }
        __syncthreads();
        const int buf = j & 1;

        // ---- S = Q K^T (16x64 per warp) ----
        float s[8][4];
        #pragma unroll
        for (int nt = 0; nt < 8; nt++)
            #pragma unroll
            for (int i = 0; i < 4; i++) s[nt][i] = 0.f;

        #pragma unroll
        for (int kk = 0; kk < HD; kk += 16) {
            unsigned a[4], bk[4][4];
            ldsm4(a, QS(base + t15, kk + hi8));
            #pragma unroll
            for (int nn = 0; nn < 4; nn++)
                ldsm4(bk[nn], KS(buf, nn * 16 + krow, kk + kc8));
            #pragma unroll
            for (int nn = 0; nn < 4; nn++) {
                hmma(s[2 * nn],     a, &bk[nn][0]);
                hmma(s[2 * nn + 1], a, &bk[nn][2]);
            }
        }
        #pragma unroll
        for (int nt = 0; nt < 8; nt++)
            #pragma unroll
            for (int i = 0; i < 4; i++) s[nt][i] *= scale;

        // ---- online softmax (rows `row`, `row+8`) ----
        float rm0 = -1e30f, rm1 = -1e30f;
        #pragma unroll
        for (int nt = 0; nt < 8; nt++) {
            rm0 = fmaxf(rm0, fmaxf(s[nt][0], s[nt][1]));
            rm1 = fmaxf(rm1, fmaxf(s[nt][2], s[nt][3]));
        }
        rm0 = fmaxf(rm0, __shfl_xor_sync(0xffffffffu, rm0, 1));
        rm0 = fmaxf(rm0, __shfl_xor_sync(0xffffffffu, rm0, 2));
        rm1 = fmaxf(rm1, __shfl_xor_sync(0xffffffffu, rm1, 1));
        rm1 = fmaxf(rm1, __shfl_xor_sync(0xffffffffu, rm1, 2));

        float mn0 = fmaxf(m0, rm0), mn1 = fmaxf(m1, rm1);
        float sc0 = __expf(m0 - mn0), sc1 = __expf(m1 - mn1);
        float ls0 = 0.f, ls1 = 0.f;

        // P in registers: C-frag pairs packed directly as m16n8k16 A-frags.
        unsigned pa[4][4];
        #pragma unroll
        for (int nt = 0; nt < 8; nt++) {
            float p0 = __expf(s[nt][0] - mn0), p1 = __expf(s[nt][1] - mn0);
            float p2 = __expf(s[nt][2] - mn1), p3 = __expf(s[nt][3] - mn1);
            ls0 += p0 + p1; ls1 += p2 + p3;
            pa[nt >> 1][(nt & 1) * 2 + 0] = packh(p0, p1);
            pa[nt >> 1][(nt & 1) * 2 + 1] = packh(p2, p3);
        }
        ls0 += __shfl_xor_sync(0xffffffffu, ls0, 1);
        ls0 += __shfl_xor_sync(0xffffffffu, ls0, 2);
        ls1 += __shfl_xor_sync(0xffffffffu, ls1, 1);
        ls1 += __shfl_xor_sync(0xffffffffu, ls1, 2);

        l0 = l0 * sc0 + ls0; l1 = l1 * sc1 + ls1;
        m0 = mn0; m1 = mn1;
        #pragma unroll
        for (int nt = 0; nt < 16; nt++) {
            o[nt][0] *= sc0; o[nt][1] *= sc0;
            o[nt][2] *= sc1; o[nt][3] *= sc1;
        }

        // ---- O += P V (16x128 per warp) ----
        #pragma unroll
        for (int kb = 0; kb < 4; kb++) {
            unsigned bv[8][4];
            #pragma unroll
            for (int nn = 0; nn < 8; nn++)
                ldsm4t(bv[nn], VS(buf, kb * 16 + t15, nn * 16 + hi8));
            #pragma unroll
            for (int nn = 0; nn < 8; nn++) {
                hmma(o[2 * nn],     pa[kb], &bv[nn][0]);
                hmma(o[2 * nn + 1], pa[kb], &bv[nn][2]);
            }
        }
        __syncthreads();
    }

    const float i0 = 1.f / l0, i1 = 1.f / l1;
    __half* Ob = O + ((size_t)(b * SEQ + q0 + row)) * DIMX + h * HD;
    #pragma unroll
    for (int nt = 0; nt < 16; nt++) {
        int c = nt * 8 + 2 * q4;
        *(__half2*)(Ob + c) = __floats2half2_rn(o[nt][0] * i0, o[nt][1] * i0);
        *(__half2*)(Ob + (size_t)8 * DIMX + c) = __floats2half2_rn(o[nt][2] * i1, o[nt][3] * i1);
    }
}

// ================= launch =================
extern "C" void kernel_launch(void* const* d_in, const int* in_sizes, int n_in,
                              void* d_out, int out_size)
{
    const float* x    = (const float*)d_in[0];
    const float* wq_w = (const float*)d_in[1];
    const float* wq_b = (const float*)d_in[2];
    const float* wk_w = (const float*)d_in[3];
    const float* wk_b = (const float*)d_in[4];
    const float* wv_w = (const float*)d_in[5];
    const float* wv_b = (const float*)d_in[6];
    const float* wo_w = (const float*)d_in[7];
    const float* wo_b = (const float*)d_in[8];
    float* out = (float*)d_out;

    __half *xh, *wqh, *wkh, *wvh, *woh, *Qh, *Kh, *Vh, *Ah;
    cudaGetSymbolAddress((void**)&xh,  g_xh);
    cudaGetSymbolAddress((void**)&wqh, g_wqh);
    cudaGetSymbolAddress((void**)&wkh, g_wkh);
    cudaGetSymbolAddress((void**)&wvh, g_wvh);
    cudaGetSymbolAddress((void**)&woh, g_woh);
    cudaGetSymbolAddress((void**)&Qh,  g_Qh);
    cudaGetSymbolAddress((void**)&Kh,  g_Kh);
    cudaGetSymbolAddress((void**)&Vh,  g_Vh);
    cudaGetSymbolAddress((void**)&Ah,  g_Ah);

    cudaFuncSetAttribute(flash16, cudaFuncAttributeMaxDynamicSharedMemorySize, FLASH_SMEM_BYTES);
    cudaFuncSetAttribute(gemm16<__half>, cudaFuncAttributeMaxDynamicSharedMemorySize, GSMEM_BYTES);
    cudaFuncSetAttribute(gemm16<float>,  cudaFuncAttributeMaxDynamicSharedMemorySize, GSMEM_BYTES);

    dim3 blk(256);
    {
        int n4;
        n4 = MTOK * DIMX / 4; f2h<<<n4 / 256, blk>>>((const float4*)x,    (__half2*)xh,  n4);
        n4 = DIMX * DIMX / 4; f2h<<<n4 / 256, blk>>>((const float4*)wq_w, (__half2*)wqh, n4);
        n4 = DIMX * KVD  / 4; f2h<<<n4 / 256, blk>>>((const float4*)wk_w, (__half2*)wkh, n4);
        n4 = DIMX * KVD  / 4; f2h<<<n4 / 256, blk>>>((const float4*)wv_w, (__half2*)wvh, n4);
        n4 = DIMX * DIMX / 4; f2h<<<n4 / 256, blk>>>((const float4*)wo_w, (__half2*)woh, n4);
    }

    gemm16<__half><<<dim3(DIMX / 128, MTOK / 128), blk, GSMEM_BYTES>>>(xh, wqh, wq_b, Qh, MTOK, DIMX, DIMX);
    gemm16<__half><<<dim3(KVD  / 128, MTOK / 128), blk, GSMEM_BYTES>>>(xh, wkh, wk_b, Kh, MTOK, KVD,  DIMX);
    gemm16<__half><<<dim3(KVD  / 128, MTOK / 128), blk, GSMEM_BYTES>>>(xh, wvh, wv_b, Vh, MTOK, KVD,  DIMX);
    flash16<<<dim3(SEQ / 128, BSZ * QH), blk, FLASH_SMEM_BYTES>>>(Qh, Kh, Vh, Ah);
    gemm16<float><<<dim3(DIMX / 128, MTOK / 128), blk, GSMEM_BYTES>>>(Ah, woh, wo_b, out, MTOK, DIMX, DIMX);
}

// round 16
// speedup vs baseline: 1.6480x; 1.0148x over previous
#include <cuda_runtime.h>
#include <cuda_fp16.h>
#include <cstdint>

#define DIMX 4096
#define QH   32
#define KVH  8
#define HD   128
#define SEQ  2048
#define BSZ  2
#define MTOK (BSZ*SEQ)      // 4096 tokens
#define KVD  (KVH*HD)       // 1024

// ---------------- fp16 scratch (static; no allocation) ----------------
__device__ __half g_xh [(size_t)MTOK * DIMX];
__device__ __half g_wqh[(size_t)DIMX * DIMX];
__device__ __half g_wkh[(size_t)DIMX * KVD];
__device__ __half g_wvh[(size_t)DIMX * KVD];
__device__ __half g_woh[(size_t)DIMX * DIMX];
__device__ __half g_Qh [(size_t)MTOK * DIMX];
__device__ __half g_Kh [(size_t)MTOK * KVD];
__device__ __half g_Vh [(size_t)MTOK * KVD];
__device__ __half g_Ah [(size_t)MTOK * DIMX];

// ---------------- helpers ----------------
__device__ __forceinline__ void ldsm4(unsigned* r, uint32_t a) {
    asm volatile("ldmatrix.sync.aligned.m8n8.x4.shared.b16 {%0,%1,%2,%3}, [%4];\n"
                 : "=r"(r[0]), "=r"(r[1]), "=r"(r[2]), "=r"(r[3]) : "r"(a));
}
__device__ __forceinline__ void ldsm4t(unsigned* r, uint32_t a) {
    asm volatile("ldmatrix.sync.aligned.m8n8.x4.trans.shared.b16 {%0,%1,%2,%3}, [%4];\n"
                 : "=r"(r[0]), "=r"(r[1]), "=r"(r[2]), "=r"(r[3]) : "r"(a));
}
__device__ __forceinline__ void hmma(float* c, const unsigned* a, const unsigned* b) {
    asm volatile("mma.sync.aligned.m16n8k16.row.col.f32.f16.f16.f32 "
                 "{%0,%1,%2,%3}, {%4,%5,%6,%7}, {%8,%9}, {%0,%1,%2,%3};\n"
                 : "+f"(c[0]), "+f"(c[1]), "+f"(c[2]), "+f"(c[3])
                 : "r"(a[0]), "r"(a[1]), "r"(a[2]), "r"(a[3]), "r"(b[0]), "r"(b[1]));
}
__device__ __forceinline__ void cpa16(uint32_t dst, const void* src) {
    asm volatile("cp.async.cg.shared.global [%0], [%1], 16;\n" :: "r"(dst), "l"(src));
}
#define CP_COMMIT() asm volatile("cp.async.commit_group;\n")
#define CP_WAIT1()  asm volatile("cp.async.wait_group 1;\n")
#define CP_WAIT0()  asm volatile("cp.async.wait_group 0;\n")

__device__ __forceinline__ void st2(float* p, float x, float y)  { *(float2*)p = make_float2(x, y); }
__device__ __forceinline__ void st2(__half* p, float x, float y) { *(__half2*)p = __floats2half2_rn(x, y); }
__device__ __forceinline__ unsigned packh(float lo, float hi) {
    __half2 h = __floats2half2_rn(lo, hi);
    return *(unsigned*)&h;
}

// ---------------- f32 -> f16 convert ----------------
__global__ __launch_bounds__(256) void f2h(const float4* __restrict__ in,
                                           __half2* __restrict__ out, int n4) {
    int i = blockIdx.x * blockDim.x + threadIdx.x;
    if (i < n4) {
        float4 v = in[i];
        out[2 * i]     = __floats2half2_rn(v.x, v.y);
        out[2 * i + 1] = __floats2half2_rn(v.z, v.w);
    }
}

// ================= GEMM fp16: C[M,N] = A[M,K] @ W[K,N] + bias =================
// UNCHANGED from R13 (1470us run): BM=128 BN=128 BK=64, 2-stage cp.async.
#define APITCH 72     // 64 + 8 halves pad
#define BPITCH 136    // 128 + 8 halves pad
#define ASTG   (128 * APITCH)            // 9216 halves
#define BSTG   (64 * BPITCH)             // 8704 halves
#define GSTGH  (ASTG + BSTG)             // 17920 halves per stage
#define GSMEM_BYTES (2 * GSTGH * 2)      // 71680 B

template<typename OutT>
__global__ __launch_bounds__(256, 2) void gemm16(
    const __half* __restrict__ A, const __half* __restrict__ W,
    const float* __restrict__ bias, OutT* __restrict__ C,
    int M, int N, int K)
{
    extern __shared__ __half smem[];
    const uint32_t sb = (uint32_t)__cvta_generic_to_shared(smem);

    const int tid = threadIdx.x, lane = tid & 31, warp = tid >> 5;
    const int wm = (warp >> 1) * 32, wn = (warp & 1) * 64;
    const int bm = blockIdx.y * 128, bn = blockIdx.x * 128;
    const int g = lane >> 2, q = lane & 3;
    const int t15 = lane & 15, hi8 = (lane >> 4) * 8;

    float acc[2][8][4];
    #pragma unroll
    for (int mt = 0; mt < 2; mt++)
        #pragma unroll
        for (int nt = 0; nt < 8; nt++)
            #pragma unroll
            for (int i = 0; i < 4; i++) acc[mt][nt][i] = 0.f;

    auto As = [&](int s, int r, int c) { return sb + (uint32_t)(s * GSTGH + r * APITCH + c) * 2u; };
    auto Bs = [&](int s, int r, int c) { return sb + (uint32_t)(s * GSTGH + ASTG + r * BPITCH + c) * 2u; };

    auto load_stage = [&](int s, int k0) {
        #pragma unroll
        for (int i = 0; i < 4; i++) {
            int id = tid + i * 256;
            int r = id >> 3, c = (id & 7) * 8;
            cpa16(As(s, r, c), A + (size_t)(bm + r) * K + k0 + c);
        }
        #pragma unroll
        for (int i = 0; i < 4; i++) {
            int id = tid + i * 256;
            int r = id >> 4, c = (id & 15) * 8;
            cpa16(Bs(s, r, c), W + (size_t)(k0 + r) * N + bn + c);
        }
        CP_COMMIT();
    };

    load_stage(0, 0);
    const int T = K >> 6;
    for (int t = 0; t < T; t++) {
        if (t + 1 < T) { load_stage((t + 1) & 1, (t + 1) * 64); CP_WAIT1(); }
        else           { CP_WAIT0(); }
        __syncthreads();
        const int s = t & 1;
        #pragma unroll
        for (int kk = 0; kk < 64; kk += 16) {
            unsigned a[2][4], bf[4][4];
            #pragma unroll
            for (int mt = 0; mt < 2; mt++)
                ldsm4(a[mt], As(s, wm + mt * 16 + t15, kk + hi8));
            #pragma unroll
            for (int nn = 0; nn < 4; nn++)
                ldsm4t(bf[nn], Bs(s, kk + t15, wn + nn * 16 + hi8));
            #pragma unroll
            for (int mt = 0; mt < 2; mt++)
                #pragma unroll
                for (int nn = 0; nn < 4; nn++) {
                    hmma(acc[mt][2 * nn],     a[mt], &bf[nn][0]);
                    hmma(acc[mt][2 * nn + 1], a[mt], &bf[nn][2]);
                }
        }
        __syncthreads();
    }

    #pragma unroll
    for (int mt = 0; mt < 2; mt++) {
        int r0 = bm + wm + mt * 16 + g;
        #pragma unroll
        for (int nt = 0; nt < 8; nt++) {
            int c0 = bn + wn + nt * 8 + q * 2;
            float b0 = bias[c0], b1 = bias[c0 + 1];
            st2(C + (size_t)r0 * N + c0,       acc[mt][nt][0] + b0, acc[mt][nt][1] + b1);
            st2(C + (size_t)(r0 + 8) * N + c0, acc[mt][nt][2] + b0, acc[mt][nt][3] + b1);
        }
    }
}

// ================= Flash attention fp16 (Br=128, Bc=128, d=128) =================
// 256 threads / 8 warps; warp w owns query rows [w*16, w*16+16).
// Bc=128: 16 j-iterations (was 32) -> half the barrier/wait/softmax overhead.
// P in registers. K/V cp.async double-buffered. occ 1, no reg cap.
// smem = Q(128x136) + 2x K(128x136) + 2x V(128x136) = 174080 B.
#define FDP 136
#define QS0 0
#define KS0 17408                        // halves
#define KSTRIDE 17408                    // per stage (128*136)
#define VS0 (KS0 + 2 * KSTRIDE)          // 52224
#define FLASH_SMEM_BYTES ((VS0 + 2 * KSTRIDE) * 2)   // 174080

__global__ __launch_bounds__(256, 1) void flash16(
    const __half* __restrict__ Q, const __half* __restrict__ Kp,
    const __half* __restrict__ Vp, __half* __restrict__ O)
{
    extern __shared__ __half fsm[];
    const uint32_t sb = (uint32_t)__cvta_generic_to_shared(fsm);

    const int tid = threadIdx.x, lane = tid & 31, warp = tid >> 5;
    const int g = lane >> 2, q4 = lane & 3;
    const int t15 = lane & 15, hi8 = (lane >> 4) * 8;
    const int krow = ((lane >> 4) << 3) | (lane & 7);
    const int kc8 = ((lane >> 3) & 1) * 8;
    const int gh = blockIdx.y;
    const int b = gh >> 5, h = gh & 31, kvh = h >> 2;
    const int q0 = blockIdx.x * 128;
    const int base = warp * 16;
    const int row = base + g;
    const float scale = 0.08838834764831845f;   // 1/sqrt(128)

    auto QS = [&](int r, int c)        { return sb + (uint32_t)(QS0 + r * FDP + c) * 2u; };
    auto KS = [&](int s, int r, int c) { return sb + (uint32_t)(KS0 + s * KSTRIDE + r * FDP + c) * 2u; };
    auto VS = [&](int s, int r, int c) { return sb + (uint32_t)(VS0 + s * KSTRIDE + r * FDP + c) * 2u; };

    auto load_kv = [&](int s, int j) {   // j in units of 128 rows
        const __half* Kb = Kp + ((size_t)(b * SEQ + j * 128)) * KVD + kvh * HD;
        const __half* Vb = Vp + ((size_t)(b * SEQ + j * 128)) * KVD + kvh * HD;
        #pragma unroll
        for (int i = 0; i < 8; i++) {
            int id = tid + i * 256;        // 0..2047
            int r = id >> 4, c = (id & 15) * 8;
            cpa16(KS(s, r, c), Kb + (size_t)r * KVD + c);
            cpa16(VS(s, r, c), Vb + (size_t)r * KVD + c);
        }
        CP_COMMIT();
    };

    load_kv(0, 0);

    // Q tile -> smem (vectorized)
    const __half* Qb = Q + ((size_t)(b * SEQ + q0)) * DIMX + h * HD;
    #pragma unroll
    for (int i = 0; i < 8; i++) {
        int id = tid + i * 256;
        int r = id >> 4, c = (id & 15) * 8;
        *(uint4*)(fsm + QS0 + r * FDP + c) = *(const uint4*)(Qb + (size_t)r * DIMX + c);
    }

    float m0 = -1e30f, m1 = -1e30f, l0 = 0.f, l1 = 0.f;
    float o[16][4];
    #pragma unroll
    for (int nt = 0; nt < 16; nt++)
        #pragma unroll
        for (int i = 0; i < 4; i++) o[nt][i] = 0.f;

    const int TJ = SEQ / 128;   // 16
    for (int j = 0; j < TJ; j++) {
        if (j + 1 < TJ) { load_kv((j + 1) & 1, j + 1); CP_WAIT1(); }
        else            { CP_WAIT0(); }
        __syncthreads();
        const int buf = j & 1;

        // ---- S = Q K^T (16x128 per warp) ----
        float s[16][4];
        #pragma unroll
        for (int nt = 0; nt < 16; nt++)
            #pragma unroll
            for (int i = 0; i < 4; i++) s[nt][i] = 0.f;

        #pragma unroll
        for (int kk = 0; kk < HD; kk += 16) {
            unsigned a[4], bk[8][4];
            ldsm4(a, QS(base + t15, kk + hi8));
            #pragma unroll
            for (int nn = 0; nn < 8; nn++)
                ldsm4(bk[nn], KS(buf, nn * 16 + krow, kk + kc8));
            #pragma unroll
            for (int nn = 0; nn < 8; nn++) {
                hmma(s[2 * nn],     a, &bk[nn][0]);
                hmma(s[2 * nn + 1], a, &bk[nn][2]);
            }
        }
        #pragma unroll
        for (int nt = 0; nt < 16; nt++)
            #pragma unroll
            for (int i = 0; i < 4; i++) s[nt][i] *= scale;

        // ---- online softmax (rows `row`, `row+8`) ----
        float rm0 = -1e30f, rm1 = -1e30f;
        #pragma unroll
        for (int nt = 0; nt < 16; nt++) {
            rm0 = fmaxf(rm0, fmaxf(s[nt][0], s[nt][1]));
            rm1 = fmaxf(rm1, fmaxf(s[nt][2], s[nt][3]));
        }
        rm0 = fmaxf(rm0, __shfl_xor_sync(0xffffffffu, rm0, 1));
        rm0 = fmaxf(rm0, __shfl_xor_sync(0xffffffffu, rm0, 2));
        rm1 = fmaxf(rm1, __shfl_xor_sync(0xffffffffu, rm1, 1));
        rm1 = fmaxf(rm1, __shfl_xor_sync(0xffffffffu, rm1, 2));

        float mn0 = fmaxf(m0, rm0), mn1 = fmaxf(m1, rm1);
        float sc0 = __expf(m0 - mn0), sc1 = __expf(m1 - mn1);
        float ls0 = 0.f, ls1 = 0.f;

        // P in registers: C-frag pairs packed directly as m16n8k16 A-frags.
        unsigned pa[8][4];
        #pragma unroll
        for (int nt = 0; nt < 16; nt++) {
            float p0 = __expf(s[nt][0] - mn0), p1 = __expf(s[nt][1] - mn0);
            float p2 = __expf(s[nt][2] - mn1), p3 = __expf(s[nt][3] - mn1);
            ls0 += p0 + p1; ls1 += p2 + p3;
            pa[nt >> 1][(nt & 1) * 2 + 0] = packh(p0, p1);
            pa[nt >> 1][(nt & 1) * 2 + 1] = packh(p2, p3);
        }
        ls0 += __shfl_xor_sync(0xffffffffu, ls0, 1);
        ls0 += __shfl_xor_sync(0xffffffffu, ls0, 2);
        ls1 += __shfl_xor_sync(0xffffffffu, ls1, 1);
        ls1 += __shfl_xor_sync(0xffffffffu, ls1, 2);

        l0 = l0 * sc0 + ls0; l1 = l1 * sc1 + ls1;
        m0 = mn0; m1 = mn1;
        #pragma unroll
        for (int nt = 0; nt < 16; nt++) {
            o[nt][0] *= sc0; o[nt][1] *= sc0;
            o[nt][2] *= sc1; o[nt][3] *= sc1;
        }

        // ---- O += P V (16x128 per warp, K-dim now 128) ----
        #pragma unroll
        for (int kb = 0; kb < 8; kb++) {
            unsigned bv[8][4];
            #pragma unroll
            for (int nn = 0; nn < 8; nn++)
                ldsm4t(bv[nn], VS(buf, kb * 16 + t15, nn * 16 + hi8));
            #pragma unroll
            for (int nn = 0; nn < 8; nn++) {
                hmma(o[2 * nn],     pa[kb], &bv[nn][0]);
                hmma(o[2 * nn + 1], pa[kb], &bv[nn][2]);
            }
        }
        __syncthreads();
    }

    const float i0 = 1.f / l0, i1 = 1.f / l1;
    __half* Ob = O + ((size_t)(b * SEQ + q0 + row)) * DIMX + h * HD;
    #pragma unroll
    for (int nt = 0; nt < 16; nt++) {
        int c = nt * 8 + 2 * q4;
        *(__half2*)(Ob + c) = __floats2half2_rn(o[nt][0] * i0, o[nt][1] * i0);
        *(__half2*)(Ob + (size_t)8 * DIMX + c) = __floats2half2_rn(o[nt][2] * i1, o[nt][3] * i1);
    }
}

// ================= launch =================
extern "C" void kernel_launch(void* const* d_in, const int* in_sizes, int n_in,
                              void* d_out, int out_size)
{
    const float* x    = (const float*)d_in[0];
    const float* wq_w = (const float*)d_in[1];
    const float* wq_b = (const float*)d_in[2];
    const float* wk_w = (const float*)d_in[3];
    const float* wk_b = (const float*)d_in[4];
    const float* wv_w = (const float*)d_in[5];
    const float* wv_b = (const float*)d_in[6];
    const float* wo_w = (const float*)d_in[7];
    const float* wo_b = (const float*)d_in[8];
    float* out = (float*)d_out;

    __half *xh, *wqh, *wkh, *wvh, *woh, *Qh, *Kh, *Vh, *Ah;
    cudaGetSymbolAddress((void**)&xh,  g_xh);
    cudaGetSymbolAddress((void**)&wqh, g_wqh);
    cudaGetSymbolAddress((void**)&wkh, g_wkh);
    cudaGetSymbolAddress((void**)&wvh, g_wvh);
    cudaGetSymbolAddress((void**)&woh, g_woh);
    cudaGetSymbolAddress((void**)&Qh,  g_Qh);
    cudaGetSymbolAddress((void**)&Kh,  g_Kh);
    cudaGetSymbolAddress((void**)&Vh,  g_Vh);
    cudaGetSymbolAddress((void**)&Ah,  g_Ah);

    cudaFuncSetAttribute(flash16, cudaFuncAttributeMaxDynamicSharedMemorySize, FLASH_SMEM_BYTES);
    cudaFuncSetAttribute(gemm16<__half>, cudaFuncAttributeMaxDynamicSharedMemorySize, GSMEM_BYTES);
    cudaFuncSetAttribute(gemm16<float>,  cudaFuncAttributeMaxDynamicSharedMemorySize, GSMEM_BYTES);

    dim3 blk(256);
    {
        int n4;
        n4 = MTOK * DIMX / 4; f2h<<<n4 / 256, blk>>>((const float4*)x,    (__half2*)xh,  n4);
        n4 = DIMX * DIMX / 4; f2h<<<n4 / 256, blk>>>((const float4*)wq_w, (__half2*)wqh, n4);
        n4 = DIMX * KVD  / 4; f2h<<<n4 / 256, blk>>>((const float4*)wk_w, (__half2*)wkh, n4);
        n4 = DIMX * KVD  / 4; f2h<<<n4 / 256, blk>>>((const float4*)wv_w, (__half2*)wvh, n4);
        n4 = DIMX * DIMX / 4; f2h<<<n4 / 256, blk>>>((const float4*)wo_w, (__half2*)woh, n4);
    }

    gemm16<__half><<<dim3(DIMX / 128, MTOK / 128), blk, GSMEM_BYTES>>>(xh, wqh, wq_b, Qh, MTOK, DIMX, DIMX);
    gemm16<__half><<<dim3(KVD  / 128, MTOK / 128), blk, GSMEM_BYTES>>>(xh, wkh, wk_b, Kh, MTOK, KVD,  DIMX);
    gemm16<__half><<<dim3(KVD  / 128, MTOK / 128), blk, GSMEM_BYTES>>>(xh, wvh, wv_b, Vh, MTOK, KVD,  DIMX);
    flash16<<<dim3(SEQ / 128, BSZ * QH), blk, FLASH_SMEM_BYTES>>>(Qh, Kh, Vh, Ah);
    gemm16<float><<<dim3(DIMX / 128, MTOK / 128), blk, GSMEM_BYTES>>>(Ah, woh, wo_b, out, MTOK, DIMX, DIMX);
}